// round 7
// baseline (speedup 1.0000x reference)
#include <cuda_runtime.h>
#include <cuda_fp16.h>
#include <cstdint>

#define G     128
#define RS    130              // padded row stride in halfs (65 half2)
#define RS2   65
#define GRS   (G*RS)
#define NL    200000
#define DX    3.125f
// cell-unit constants: CC = ICC*log2(e)*DX^2, KW2C = KW2/DX^2
#define CC    0.99658f
#define KW2C  2.8952918f
#define TFRAC 0.2016f
#define THREADS 512
#define LPT   4
#define LPC   (THREADS*LPT)            // 2048
#define NCTA  ((NL + LPC - 1)/LPC)     // 98 per axis

#define SLICE_BYTES  (GRS*2)           // 33280
#define SMEM_BYTES   (128 + 2*SLICE_BYTES)   // 66688 -> 2 CTA/SM

// fp16 slice-major padded volumes, one per axis
__device__ __half g_tx[G*G*RS];
__device__ __half g_ty[G*G*RS];
__device__ __half g_tz[G*G*RS];

// One fused transform: read image[i][j][k] tile once, emit all three layouts.
__global__ void trans_all_kernel(const float* __restrict__ img) {
    __shared__ float tile[32][33];
    const int i  = blockIdx.z;
    const int jb = blockIdx.x * 32;
    const int kb = blockIdx.y * 32;
    const int tx = threadIdx.x, ty = threadIdx.y;   // (32, 8)
    #pragma unroll
    for (int r = 0; r < 32; r += 8) {
        const int j = jb + ty + r;
        const float v = img[(i*G + j)*G + kb + tx];
        tile[ty + r][tx] = v;
        const __half h = __float2half(v);
        g_tx[(i*G + j)*RS + kb + tx] = h;
        g_ty[(j*G + i)*RS + kb + tx] = h;
    }
    __syncthreads();
    #pragma unroll
    for (int r = 0; r < 32; r += 8)
        g_tz[((kb + ty + r)*G + i)*RS + jb + tx] = __float2half(tile[tx][ty + r]);
}

// ---------------- TMA / mbarrier helpers (proven R5 versions) ----------------
__device__ __forceinline__ void mbar_init(uint32_t mbar, uint32_t count) {
    asm volatile("mbarrier.init.shared::cta.b64 [%0], %1;" :: "r"(mbar), "r"(count) : "memory");
}
__device__ __forceinline__ void mbar_expect_tx(uint32_t mbar, uint32_t bytes) {
    asm volatile("mbarrier.arrive.expect_tx.shared::cta.b64 _, [%0], %1;"
                 :: "r"(mbar), "r"(bytes) : "memory");
}
__device__ __forceinline__ void mbar_wait(uint32_t mbar, uint32_t phase) {
    asm volatile(
        "{\n\t"
        ".reg .pred P1;\n\t"
        "LAB_WAIT_%=:\n\t"
        "mbarrier.try_wait.parity.acquire.cta.shared::cta.b64 P1, [%0], %1, 0x989680;\n\t"
        "@P1 bra LAB_DONE_%=;\n\t"
        "bra.uni LAB_WAIT_%=;\n\t"
        "LAB_DONE_%=:\n\t"
        "}"
        :: "r"(mbar), "r"(phase) : "memory");
}
__device__ __forceinline__ void bulk_g2s(uint32_t dst, const void* src, uint32_t bytes, uint32_t mbar) {
    asm volatile("cp.async.bulk.shared::cluster.global.mbarrier::complete_tx::bytes [%0], [%1], %2, [%3];"
                 :: "r"(dst), "l"(src), "r"(bytes), "r"(mbar) : "memory");
}

__global__ __launch_bounds__(THREADS, 2)
void proj_kernel(const float* __restrict__ lx,
                 const float* __restrict__ ly,
                 const float* __restrict__ lz,
                 float* __restrict__ out)
{
    extern __shared__ __align__(128) unsigned char smem_raw[];
    const uint32_t smem_base = (uint32_t)__cvta_generic_to_shared(smem_raw);
    const uint32_t mbar0 = smem_base;
    __half* sbuf = (__half*)(smem_raw + 128);

    const int axis = blockIdx.y;
    const int tid  = threadIdx.x;
    const int cta_base = blockIdx.x * LPC;

    const float* lors;
    const __half* vol;
    int q0, q1;
    if (axis == 0)      { lors = lx; vol = g_tx; q0 = 1; q1 = 2; }
    else if (axis == 1) { lors = ly; vol = g_ty; q0 = 0; q1 = 2; }
    else                { lors = lz; vol = g_tz; q0 = 0; q1 = 1; }

    // per-LOR params in CELL units. Scan-axis coords are exactly +/-200 -> dvz=400.
    // u(k) = (P0 + (k+0.5)*DX/400*dv)*INVDX + 64 = ua0 + k*dd,  dd = dv/400
    float ua0[LPT], va0[LPT], ddx[LPT], ddy[LPT], total[LPT];
    #pragma unroll
    for (int l = 0; l < LPT; l++) {
        int gi = cta_base + l*THREADS + tid;
        int lr = gi < NL ? gi : NL - 1;
        const float* L6 = lors + lr * 6;
        float px = L6[q0], py = L6[q1];
        ddx[l] = (L6[q0+3] - px) * (1.0f/400.0f);
        ddy[l] = (L6[q1+3] - py) * (1.0f/400.0f);
        ua0[l] = fmaf(px, 0.32f, 64.0f) + 0.5f * ddx[l];
        va0[l] = fmaf(py, 0.32f, 64.0f) + 0.5f * ddy[l];
        total[l] = 0.0f;
    }

    const __half2 nCC2  = __float2half2_rn(-CC);
    const __half2 KW2C2 = __float2half2_rn(KW2C);
    const __half2 zero2 = __float2half2_rn(0.0f);

    if (tid == 0) {
        mbar_init(mbar0,     1);
        mbar_init(mbar0 + 8, 1);
        asm volatile("fence.proxy.async.shared::cta;" ::: "memory");
    }
    __syncthreads();
    if (tid == 0) {
        mbar_expect_tx(mbar0,     SLICE_BYTES);
        bulk_g2s(smem_base + 128,               vol,        SLICE_BYTES, mbar0);
        mbar_expect_tx(mbar0 + 8, SLICE_BYTES);
        bulk_g2s(smem_base + 128 + SLICE_BYTES, vol + GRS,  SLICE_BYTES, mbar0 + 8);
    }

    float kf = 0.0f;
    for (int k = 0; k < G; k++) {
        const int b = k & 1;
        mbar_wait(mbar0 + b*8, (k >> 1) & 1);
        const __half2* slice = (const __half2*)(sbuf + b * GRS);

        #pragma unroll
        for (int l = 0; l < LPT; l++) {
            const float ua = fmaf(kf, ddx[l], ua0[l]);
            const float va = fmaf(kf, ddy[l], va0[l]);

            float af = floorf(ua - TFRAC) - 1.0f;
            af = fminf(fmaxf(af, 0.0f), 124.0f);
            float cf = floorf(va - TFRAC) - 1.0f;
            cf = fminf(fmaxf(cf, 0.0f), 122.0f);
            const int alo = (int)af;
            const int cE  = ((int)cf) & ~1;

            const float e = af + 0.5f - ua;          // row offset (cells)
            const float f = (float)cE + 0.5f - va;   // col offset (cells)

            // column (f+m)^2 chain, m = 0..5
            const float t0 = f*f;
            float inc = fmaf(2.0f, f, 1.0f);
            const float t1 = t0 + inc; inc += 2.0f;
            const float t2 = t1 + inc; inc += 2.0f;
            const float t3 = t2 + inc; inc += 2.0f;
            const float t4 = t3 + inc; inc += 2.0f;
            const float t5 = t4 + inc;
            const __half2 S0 = __floats2half2_rn(t0, t1);
            const __half2 S1 = __floats2half2_rn(t2, t3);
            const __half2 S2 = __floats2half2_rn(t4, t5);
            const __half2 P0 = h2exp2(__hmul2(S0, nCC2));
            const __half2 P1 = h2exp2(__hmul2(S1, nCC2));
            const __half2 P2 = h2exp2(__hmul2(S2, nCC2));

            // row (e+a)^2 chain, a = 0..3, packed: weights + limits for all rows upfront
            const float u0 = e*e;
            float ri = fmaf(2.0f, e, 1.0f);
            const float u1 = u0 + ri; ri += 2.0f;
            const float u2 = u1 + ri; ri += 2.0f;
            const float u3 = u2 + ri;
            const __half2 X01 = __floats2half2_rn(u0, u1);
            const __half2 X23 = __floats2half2_rn(u2, u3);
            const __half2 W01 = h2exp2(__hmul2(X01, nCC2));
            const __half2 W23 = h2exp2(__hmul2(X23, nCC2));
            const __half2 L01 = __hsub2(KW2C2, X01);
            const __half2 L23 = __hsub2(KW2C2, X23);

            __half2 lb[4], wb[4];
            lb[0] = __low2half2(L01);  lb[1] = __high2half2(L01);
            lb[2] = __low2half2(L23);  lb[3] = __high2half2(L23);
            wb[0] = __low2half2(W01);  wb[1] = __high2half2(W01);
            wb[2] = __low2half2(W23);  wb[3] = __high2half2(W23);

            const __half2* rp = slice + alo * RS2 + (cE >> 1);
            __half2 acc2 = zero2;

            #pragma unroll
            for (int a = 0; a < 4; a++) {
                const __half2 V0 = rp[0];
                const __half2 V1 = rp[1];
                const __half2 V2 = rp[2];
                __half2 r2 = __hmul2(__hmul2(__hle2(S0, lb[a]), P0), V0);
                r2 = __hfma2(__hmul2(__hle2(S1, lb[a]), P1), V1, r2);
                r2 = __hfma2(__hmul2(__hle2(S2, lb[a]), P2), V2, r2);
                acc2 = __hfma2(wb[a], r2, acc2);
                rp += RS2;
            }

            const float2 fr = __half22float2(acc2);
            total[l] += fr.x + fr.y;
        }

        __syncthreads();   // all reads of buffer b complete before refill
        if (tid == 0 && k + 2 < G) {
            mbar_expect_tx(mbar0 + b*8, SLICE_BYTES);
            bulk_g2s(smem_base + 128 + b*SLICE_BYTES,
                     vol + (size_t)(k + 2)*GRS, SLICE_BYTES, mbar0 + b*8);
        }
        kf += 1.0f;
    }

    #pragma unroll
    for (int l = 0; l < LPT; l++) {
        int gi = cta_base + l*THREADS + tid;
        if (gi < NL) {
            // path = DX * sqrt(ddx^2 + ddy^2 + 1)
            float sfac = sqrtf(fmaf(ddx[l], ddx[l], fmaf(ddy[l], ddy[l], 1.0f)));
            out[axis * NL + gi] = total[l] * DX * sfac;
        }
    }
}

extern "C" void kernel_launch(void* const* d_in, const int* in_sizes, int n_in,
                              void* d_out, int out_size)
{
    (void)in_sizes; (void)n_in; (void)out_size;
    const float* image = (const float*)d_in[0];
    const float* xl    = (const float*)d_in[1];
    const float* yl    = (const float*)d_in[2];
    const float* zl    = (const float*)d_in[3];
    float* out = (float*)d_out;

    static bool attr_set = false;
    if (!attr_set) {
        cudaFuncSetAttribute(proj_kernel, cudaFuncAttributeMaxDynamicSharedMemorySize, SMEM_BYTES);
        attr_set = true;
    }

    trans_all_kernel<<<dim3(4, 4, G), dim3(32, 8)>>>(image);

    dim3 grid(NCTA, 3);
    proj_kernel<<<grid, THREADS, SMEM_BYTES>>>(xl, yl, zl, out);
}

// round 8
// speedup vs baseline: 1.0023x; 1.0023x over previous
#include <cuda_runtime.h>
#include <cuda_fp16.h>
#include <cstdint>

#define G     128
#define RS    130              // padded row stride in halfs (65 half2)
#define RS2   65
#define GRS   (G*RS)
#define NL    200000
#define DX    3.125f
// cell-unit constants: CC = ICC*log2(e)*DX^2, KW2C = KW2/DX^2
#define CC    0.99658f
#define KW2C  2.8952918f
#define TFRAC 0.2016f
#define THREADS 512
#define LPT   4
#define LPC   (THREADS*LPT)            // 2048
#define NCTA  ((NL + LPC - 1)/LPC)     // 98 per axis

#define SLICE_BYTES  (GRS*2)           // 33280
#define SMEM_BYTES   (128 + 2*SLICE_BYTES)   // 66688 -> 2 CTA/SM

// fp16 slice-major padded volumes, one per axis
__device__ __half g_tx[G*G*RS];
__device__ __half g_ty[G*G*RS];
__device__ __half g_tz[G*G*RS];

// One fused transform: read image[i][j][k] tile once, emit all three layouts.
__global__ void trans_all_kernel(const float* __restrict__ img) {
    __shared__ float tile[32][33];
    const int i  = blockIdx.z;
    const int jb = blockIdx.x * 32;
    const int kb = blockIdx.y * 32;
    const int tx = threadIdx.x, ty = threadIdx.y;   // (32, 8)
    #pragma unroll
    for (int r = 0; r < 32; r += 8) {
        const int j = jb + ty + r;
        const float v = img[(i*G + j)*G + kb + tx];
        tile[ty + r][tx] = v;
        const __half h = __float2half(v);
        g_tx[(i*G + j)*RS + kb + tx] = h;
        g_ty[(j*G + i)*RS + kb + tx] = h;
    }
    __syncthreads();
    #pragma unroll
    for (int r = 0; r < 32; r += 8)
        g_tz[((kb + ty + r)*G + i)*RS + jb + tx] = __float2half(tile[tx][ty + r]);
}

// ---------------- TMA / mbarrier helpers (proven R5 versions) ----------------
__device__ __forceinline__ void mbar_init(uint32_t mbar, uint32_t count) {
    asm volatile("mbarrier.init.shared::cta.b64 [%0], %1;" :: "r"(mbar), "r"(count) : "memory");
}
__device__ __forceinline__ void mbar_expect_tx(uint32_t mbar, uint32_t bytes) {
    asm volatile("mbarrier.arrive.expect_tx.shared::cta.b64 _, [%0], %1;"
                 :: "r"(mbar), "r"(bytes) : "memory");
}
__device__ __forceinline__ void mbar_wait(uint32_t mbar, uint32_t phase) {
    asm volatile(
        "{\n\t"
        ".reg .pred P1;\n\t"
        "LAB_WAIT_%=:\n\t"
        "mbarrier.try_wait.parity.acquire.cta.shared::cta.b64 P1, [%0], %1, 0x989680;\n\t"
        "@P1 bra LAB_DONE_%=;\n\t"
        "bra.uni LAB_WAIT_%=;\n\t"
        "LAB_DONE_%=:\n\t"
        "}"
        :: "r"(mbar), "r"(phase) : "memory");
}
__device__ __forceinline__ void bulk_g2s(uint32_t dst, const void* src, uint32_t bytes, uint32_t mbar) {
    asm volatile("cp.async.bulk.shared::cluster.global.mbarrier::complete_tx::bytes [%0], [%1], %2, [%3];"
                 :: "r"(dst), "l"(src), "r"(bytes), "r"(mbar) : "memory");
}

__global__ __launch_bounds__(THREADS, 2)
void proj_kernel(const float* __restrict__ lx,
                 const float* __restrict__ ly,
                 const float* __restrict__ lz,
                 float* __restrict__ out)
{
    extern __shared__ __align__(128) unsigned char smem_raw[];
    const uint32_t smem_base = (uint32_t)__cvta_generic_to_shared(smem_raw);
    const uint32_t mbar0 = smem_base;
    __half* sbuf = (__half*)(smem_raw + 128);

    const int axis = blockIdx.y;
    const int tid  = threadIdx.x;
    const int cta_base = blockIdx.x * LPC;

    const float* lors;
    const __half* vol;
    int q0, q1;
    if (axis == 0)      { lors = lx; vol = g_tx; q0 = 1; q1 = 2; }
    else if (axis == 1) { lors = ly; vol = g_ty; q0 = 0; q1 = 2; }
    else                { lors = lz; vol = g_tz; q0 = 0; q1 = 1; }

    // per-LOR params in CELL units. Scan-axis coords are exactly +/-200 -> dvz=400.
    // u(k) = (P0 + (k+0.5)*DX/400*dv)*INVDX + 64 = ua0 + k*dd,  dd = dv/400
    float ua0[LPT], va0[LPT], ddx[LPT], ddy[LPT], total[LPT];
    #pragma unroll
    for (int l = 0; l < LPT; l++) {
        int gi = cta_base + l*THREADS + tid;
        int lr = gi < NL ? gi : NL - 1;
        const float* L6 = lors + lr * 6;
        float px = L6[q0], py = L6[q1];
        ddx[l] = (L6[q0+3] - px) * (1.0f/400.0f);
        ddy[l] = (L6[q1+3] - py) * (1.0f/400.0f);
        ua0[l] = fmaf(px, 0.32f, 64.0f) + 0.5f * ddx[l];
        va0[l] = fmaf(py, 0.32f, 64.0f) + 0.5f * ddy[l];
        total[l] = 0.0f;
    }

    const __half2 nCC2  = __float2half2_rn(-CC);
    const __half2 KW2C2 = __float2half2_rn(KW2C);
    const __half2 zero2 = __float2half2_rn(0.0f);

    if (tid == 0) {
        mbar_init(mbar0,     1);
        mbar_init(mbar0 + 8, 1);
        asm volatile("fence.proxy.async.shared::cta;" ::: "memory");
    }
    __syncthreads();
    if (tid == 0) {
        mbar_expect_tx(mbar0,     SLICE_BYTES);
        bulk_g2s(smem_base + 128,               vol,        SLICE_BYTES, mbar0);
        mbar_expect_tx(mbar0 + 8, SLICE_BYTES);
        bulk_g2s(smem_base + 128 + SLICE_BYTES, vol + GRS,  SLICE_BYTES, mbar0 + 8);
    }

    float kf = 0.0f;
    for (int k = 0; k < G; k++) {
        const int b = k & 1;
        mbar_wait(mbar0 + b*8, (k >> 1) & 1);
        const __half2* slice = (const __half2*)(sbuf + b * GRS);

        #pragma unroll
        for (int l = 0; l < LPT; l++) {
            const float ua = fmaf(kf, ddx[l], ua0[l]);
            const float va = fmaf(kf, ddy[l], va0[l]);

            float af = floorf(ua - TFRAC) - 1.0f;
            af = fminf(fmaxf(af, 0.0f), 124.0f);
            float cf = floorf(va - TFRAC) - 1.0f;
            cf = fminf(fmaxf(cf, 0.0f), 122.0f);
            const int alo = (int)af;
            const int cE  = ((int)cf) & ~1;

            const float e = af + 0.5f - ua;          // row offset (cells)
            const float f = (float)cE + 0.5f - va;   // col offset (cells)

            // column (f+m)^2 chain, m = 0..5
            const float t0 = f*f;
            float inc = fmaf(2.0f, f, 1.0f);
            const float t1 = t0 + inc; inc += 2.0f;
            const float t2 = t1 + inc; inc += 2.0f;
            const float t3 = t2 + inc; inc += 2.0f;
            const float t4 = t3 + inc; inc += 2.0f;
            const float t5 = t4 + inc;
            const __half2 S0 = __floats2half2_rn(t0, t1);
            const __half2 S1 = __floats2half2_rn(t2, t3);
            const __half2 S2 = __floats2half2_rn(t4, t5);
            const __half2 P0 = h2exp2(__hmul2(S0, nCC2));
            const __half2 P1 = h2exp2(__hmul2(S1, nCC2));
            const __half2 P2 = h2exp2(__hmul2(S2, nCC2));

            // row (e+a)^2 chain, a = 0..3, packed: weights + limits for all rows upfront
            const float u0 = e*e;
            float ri = fmaf(2.0f, e, 1.0f);
            const float u1 = u0 + ri; ri += 2.0f;
            const float u2 = u1 + ri; ri += 2.0f;
            const float u3 = u2 + ri;
            const __half2 X01 = __floats2half2_rn(u0, u1);
            const __half2 X23 = __floats2half2_rn(u2, u3);
            const __half2 W01 = h2exp2(__hmul2(X01, nCC2));
            const __half2 W23 = h2exp2(__hmul2(X23, nCC2));
            const __half2 L01 = __hsub2(KW2C2, X01);
            const __half2 L23 = __hsub2(KW2C2, X23);

            __half2 lb[4], wb[4];
            lb[0] = __low2half2(L01);  lb[1] = __high2half2(L01);
            lb[2] = __low2half2(L23);  lb[3] = __high2half2(L23);
            wb[0] = __low2half2(W01);  wb[1] = __high2half2(W01);
            wb[2] = __low2half2(W23);  wb[3] = __high2half2(W23);

            const __half2* rp = slice + alo * RS2 + (cE >> 1);
            __half2 acc2 = zero2;

            #pragma unroll
            for (int a = 0; a < 4; a++) {
                const __half2 V0 = rp[0];
                const __half2 V1 = rp[1];
                const __half2 V2 = rp[2];
                __half2 r2 = __hmul2(__hmul2(__hle2(S0, lb[a]), P0), V0);
                r2 = __hfma2(__hmul2(__hle2(S1, lb[a]), P1), V1, r2);
                r2 = __hfma2(__hmul2(__hle2(S2, lb[a]), P2), V2, r2);
                acc2 = __hfma2(wb[a], r2, acc2);
                rp += RS2;
            }

            const float2 fr = __half22float2(acc2);
            total[l] += fr.x + fr.y;
        }

        __syncthreads();   // all reads of buffer b complete before refill
        if (tid == 0 && k + 2 < G) {
            mbar_expect_tx(mbar0 + b*8, SLICE_BYTES);
            bulk_g2s(smem_base + 128 + b*SLICE_BYTES,
                     vol + (size_t)(k + 2)*GRS, SLICE_BYTES, mbar0 + b*8);
        }
        kf += 1.0f;
    }

    #pragma unroll
    for (int l = 0; l < LPT; l++) {
        int gi = cta_base + l*THREADS + tid;
        if (gi < NL) {
            // path = DX * sqrt(ddx^2 + ddy^2 + 1)
            float sfac = sqrtf(fmaf(ddx[l], ddx[l], fmaf(ddy[l], ddy[l], 1.0f)));
            out[axis * NL + gi] = total[l] * DX * sfac;
        }
    }
}

extern "C" void kernel_launch(void* const* d_in, const int* in_sizes, int n_in,
                              void* d_out, int out_size)
{
    (void)in_sizes; (void)n_in; (void)out_size;
    const float* image = (const float*)d_in[0];
    const float* xl    = (const float*)d_in[1];
    const float* yl    = (const float*)d_in[2];
    const float* zl    = (const float*)d_in[3];
    float* out = (float*)d_out;

    static bool attr_set = false;
    if (!attr_set) {
        cudaFuncSetAttribute(proj_kernel, cudaFuncAttributeMaxDynamicSharedMemorySize, SMEM_BYTES);
        attr_set = true;
    }

    trans_all_kernel<<<dim3(4, 4, G), dim3(32, 8)>>>(image);

    dim3 grid(NCTA, 3);
    proj_kernel<<<grid, THREADS, SMEM_BYTES>>>(xl, yl, zl, out);
}

// round 9
// speedup vs baseline: 1.1679x; 1.1652x over previous
#include <cuda_runtime.h>
#include <cuda_fp16.h>
#include <cstdint>

#define G     128
#define RSB   132              // padded row stride in BYTES (33 words)
#define GRSB  (G*RSB)          // 16896 bytes per slice
#define NL    200000
#define DX    3.125f
// cell-unit constants: CC = ICC*log2(e)*DX^2, KW2C = KW2/DX^2
#define CC    0.99658f
#define KW2C  2.8952918f
#define TFRAC 0.2016f
#define THREADS 512
#define LPT   4
#define LPC   (THREADS*LPT)            // 2048
#define NCTA  ((NL + LPC - 1)/LPC)     // 98 per axis

#define SLICE_BYTES  GRSB
#define SMEM_BYTES   (128 + 2*SLICE_BYTES)   // 33920

// u8 slice-major padded volumes, one per axis
__device__ uint8_t g_tx[G*G*RSB];
__device__ uint8_t g_ty[G*G*RSB];
__device__ uint8_t g_tz[G*G*RSB];

__device__ __forceinline__ uint8_t quant_u8(float v) {
    int q = (int)floorf(v * 256.0f);
    return (uint8_t)min(max(q, 0), 255);
}

// One fused transform: read image[i][j][k] tile once, emit all three u8 layouts.
__global__ void trans_all_kernel(const float* __restrict__ img) {
    __shared__ float tile[32][33];
    const int i  = blockIdx.z;
    const int jb = blockIdx.x * 32;
    const int kb = blockIdx.y * 32;
    const int tx = threadIdx.x, ty = threadIdx.y;   // (32, 8)
    #pragma unroll
    for (int r = 0; r < 32; r += 8) {
        const int j = jb + ty + r;
        const float v = img[(i*G + j)*G + kb + tx];
        tile[ty + r][tx] = v;
        const uint8_t q = quant_u8(v);
        g_tx[(i*G + j)*RSB + kb + tx] = q;
        g_ty[(j*G + i)*RSB + kb + tx] = q;
    }
    __syncthreads();
    #pragma unroll
    for (int r = 0; r < 32; r += 8)
        g_tz[((kb + ty + r)*G + i)*RSB + jb + tx] = quant_u8(tile[tx][ty + r]);
}

// ---------------- TMA / mbarrier helpers (proven) ----------------
__device__ __forceinline__ void mbar_init(uint32_t mbar, uint32_t count) {
    asm volatile("mbarrier.init.shared::cta.b64 [%0], %1;" :: "r"(mbar), "r"(count) : "memory");
}
__device__ __forceinline__ void mbar_expect_tx(uint32_t mbar, uint32_t bytes) {
    asm volatile("mbarrier.arrive.expect_tx.shared::cta.b64 _, [%0], %1;"
                 :: "r"(mbar), "r"(bytes) : "memory");
}
__device__ __forceinline__ void mbar_wait(uint32_t mbar, uint32_t phase) {
    asm volatile(
        "{\n\t"
        ".reg .pred P1;\n\t"
        "LAB_WAIT_%=:\n\t"
        "mbarrier.try_wait.parity.acquire.cta.shared::cta.b64 P1, [%0], %1, 0x989680;\n\t"
        "@P1 bra LAB_DONE_%=;\n\t"
        "bra.uni LAB_WAIT_%=;\n\t"
        "LAB_DONE_%=:\n\t"
        "}"
        :: "r"(mbar), "r"(phase) : "memory");
}
__device__ __forceinline__ void bulk_g2s(uint32_t dst, const void* src, uint32_t bytes, uint32_t mbar) {
    asm volatile("cp.async.bulk.shared::cluster.global.mbarrier::complete_tx::bytes [%0], [%1], %2, [%3];"
                 :: "r"(dst), "l"(src), "r"(bytes), "r"(mbar) : "memory");
}

__global__ __launch_bounds__(THREADS, 2)
void proj_kernel(const float* __restrict__ lx,
                 const float* __restrict__ ly,
                 const float* __restrict__ lz,
                 float* __restrict__ out)
{
    extern __shared__ __align__(128) unsigned char smem_raw[];
    const uint32_t smem_base = (uint32_t)__cvta_generic_to_shared(smem_raw);
    const uint32_t mbar0 = smem_base;
    uint8_t* sbuf = (uint8_t*)(smem_raw + 128);

    const int axis = blockIdx.y;
    const int tid  = threadIdx.x;
    const int cta_base = blockIdx.x * LPC;

    const float* lors;
    const uint8_t* vol;
    int q0, q1;
    if (axis == 0)      { lors = lx; vol = g_tx; q0 = 1; q1 = 2; }
    else if (axis == 1) { lors = ly; vol = g_ty; q0 = 0; q1 = 2; }
    else                { lors = lz; vol = g_tz; q0 = 0; q1 = 1; }

    // per-LOR params in CELL units. Scan-axis coords are exactly +/-200 -> dvz=400.
    float ua0[LPT], va0[LPT], ddx[LPT], ddy[LPT], total[LPT];
    #pragma unroll
    for (int l = 0; l < LPT; l++) {
        int gi = cta_base + l*THREADS + tid;
        int lr = gi < NL ? gi : NL - 1;
        const float* L6 = lors + lr * 6;
        float px = L6[q0], py = L6[q1];
        ddx[l] = (L6[q0+3] - px) * (1.0f/400.0f);
        ddy[l] = (L6[q1+3] - py) * (1.0f/400.0f);
        ua0[l] = fmaf(px, 0.32f, 64.0f) + 0.5f * ddx[l];
        va0[l] = fmaf(py, 0.32f, 64.0f) + 0.5f * ddy[l];
        total[l] = 0.0f;
    }

    const __half2 nCC2  = __float2half2_rn(-CC);
    const __half2 KW2C2 = __float2half2_rn(KW2C);
    const __half2 zero2 = __float2half2_rn(0.0f);
    const __half2 B10235 = __float2half2_rn(1023.5f);   // 1024 bias - 0.5 decode offset

    if (tid == 0) {
        mbar_init(mbar0,     1);
        mbar_init(mbar0 + 8, 1);
        asm volatile("fence.proxy.async.shared::cta;" ::: "memory");
    }
    __syncthreads();
    if (tid == 0) {
        mbar_expect_tx(mbar0,     SLICE_BYTES);
        bulk_g2s(smem_base + 128,               vol,         SLICE_BYTES, mbar0);
        mbar_expect_tx(mbar0 + 8, SLICE_BYTES);
        bulk_g2s(smem_base + 128 + SLICE_BYTES, vol + GRSB,  SLICE_BYTES, mbar0 + 8);
    }

    float kf = 0.0f;
    for (int k = 0; k < G; k++) {
        const int b = k & 1;
        mbar_wait(mbar0 + b*8, (k >> 1) & 1);
        const uint8_t* slice = sbuf + b * GRSB;

        #pragma unroll
        for (int l = 0; l < LPT; l++) {
            const float ua = fmaf(kf, ddx[l], ua0[l]);
            const float va = fmaf(kf, ddy[l], va0[l]);

            float af = floorf(ua - TFRAC) - 1.0f;
            af = fminf(fmaxf(af, 0.0f), 124.0f);
            float cf = floorf(va - TFRAC) - 1.0f;
            cf = fminf(fmaxf(cf, 0.0f), 124.0f);
            const int alo = (int)af;
            const int clo = (int)cf;
            const int d   = clo & 3;
            const int cW  = clo - d;                       // word-aligned byte base
            const uint32_t selp = 0x3210u + (uint32_t)d * 0x1111u;

            const float e = af + 0.5f - ua;          // row offset (cells)
            const float f = cf + 0.5f - va;          // col offset (cells)

            // column (f+m)^2 chain, m = 0..3 (exact 4-col window)
            const float t0 = f*f;
            float inc = fmaf(2.0f, f, 1.0f);
            const float t1 = t0 + inc; inc += 2.0f;
            const float t2 = t1 + inc; inc += 2.0f;
            const float t3 = t2 + inc;
            const __half2 S0 = __floats2half2_rn(t0, t1);
            const __half2 S1 = __floats2half2_rn(t2, t3);
            const __half2 P0 = h2exp2(__hmul2(S0, nCC2));
            const __half2 P1 = h2exp2(__hmul2(S1, nCC2));

            // row (e+a)^2 chain, a = 0..3, packed weights + limits
            const float u0 = e*e;
            float ri = fmaf(2.0f, e, 1.0f);
            const float u1 = u0 + ri; ri += 2.0f;
            const float u2 = u1 + ri; ri += 2.0f;
            const float u3 = u2 + ri;
            const __half2 X01 = __floats2half2_rn(u0, u1);
            const __half2 X23 = __floats2half2_rn(u2, u3);
            const __half2 W01 = h2exp2(__hmul2(X01, nCC2));
            const __half2 W23 = h2exp2(__hmul2(X23, nCC2));
            const __half2 L01 = __hsub2(KW2C2, X01);
            const __half2 L23 = __hsub2(KW2C2, X23);

            __half2 lb[4], wb[4];
            lb[0] = __low2half2(L01);  lb[1] = __high2half2(L01);
            lb[2] = __low2half2(L23);  lb[3] = __high2half2(L23);
            wb[0] = __low2half2(W01);  wb[1] = __high2half2(W01);
            wb[2] = __low2half2(W23);  wb[3] = __high2half2(W23);

            const uint8_t* rp = slice + alo * RSB + cW;
            __half2 acc2 = zero2;

            #pragma unroll
            for (int a = 0; a < 4; a++) {
                const uint32_t w0 = *(const uint32_t*)(rp);
                const uint32_t w1 = *(const uint32_t*)(rp + 4);
                const uint32_t p  = __byte_perm(w0, w1, selp);       // 4 needed cols
                const uint32_t e0 = __byte_perm(p, 0x64646464u, 0x4140u);
                const uint32_t e1 = __byte_perm(p, 0x64646464u, 0x4342u);
                const __half2 V0 = __hsub2(*(const __half2*)&e0, B10235);  // q+0.5 exact
                const __half2 V1 = __hsub2(*(const __half2*)&e1, B10235);

                __half2 r2 = __hmul2(__hmul2(__hle2(S0, lb[a]), P0), V0);
                r2 = __hfma2(__hmul2(__hle2(S1, lb[a]), P1), V1, r2);
                acc2 = __hfma2(wb[a], r2, acc2);
                rp += RSB;
            }

            const float2 fr = __half22float2(acc2);
            total[l] += fr.x + fr.y;
        }

        __syncthreads();   // all reads of buffer b complete before refill
        if (tid == 0 && k + 2 < G) {
            mbar_expect_tx(mbar0 + b*8, SLICE_BYTES);
            bulk_g2s(smem_base + 128 + b*SLICE_BYTES,
                     vol + (size_t)(k + 2)*GRSB, SLICE_BYTES, mbar0 + b*8);
        }
        kf += 1.0f;
    }

    #pragma unroll
    for (int l = 0; l < LPT; l++) {
        int gi = cta_base + l*THREADS + tid;
        if (gi < NL) {
            // path = DX * sqrt(ddx^2 + ddy^2 + 1); u8 decode scale 1/256
            float sfac = sqrtf(fmaf(ddx[l], ddx[l], fmaf(ddy[l], ddy[l], 1.0f)));
            out[axis * NL + gi] = total[l] * (DX / 256.0f) * sfac;
        }
    }
}

extern "C" void kernel_launch(void* const* d_in, const int* in_sizes, int n_in,
                              void* d_out, int out_size)
{
    (void)in_sizes; (void)n_in; (void)out_size;
    const float* image = (const float*)d_in[0];
    const float* xl    = (const float*)d_in[1];
    const float* yl    = (const float*)d_in[2];
    const float* zl    = (const float*)d_in[3];
    float* out = (float*)d_out;

    static bool attr_set = false;
    if (!attr_set) {
        cudaFuncSetAttribute(proj_kernel, cudaFuncAttributeMaxDynamicSharedMemorySize, SMEM_BYTES);
        attr_set = true;
    }

    trans_all_kernel<<<dim3(4, 4, G), dim3(32, 8)>>>(image);

    dim3 grid(NCTA, 3);
    proj_kernel<<<grid, THREADS, SMEM_BYTES>>>(xl, yl, zl, out);
}

// round 10
// speedup vs baseline: 1.2803x; 1.0962x over previous
#include <cuda_runtime.h>
#include <cuda_fp16.h>
#include <cstdint>

#define G     128
#define RSB   132              // padded row stride in BYTES (33 words)
#define GRSB  (G*RSB)          // 16896 bytes per slice
#define NL    200000
#define DX    3.125f
// cell-unit constants: CC = ICC*log2(e)*DX^2, KW2C = KW2/DX^2
#define CC    0.99658f
#define KW2C  2.8952918f
#define TFRAC 0.2016f
#define EOFF  (-0.7016f)       // 0.5 - TFRAC - 1
#define THREADS 512
#define LPT   4
#define LPC   (THREADS*LPT)            // 2048
#define NCTA  ((NL + LPC - 1)/LPC)     // 98 per axis
#define NSTAGE 4

#define SLICE_BYTES  GRSB
#define SMEM_BYTES   (128 + NSTAGE*SLICE_BYTES)   // 67712 -> 2 CTA/SM

// u8 slice-major padded volumes, one per axis
__device__ uint8_t g_tx[G*G*RSB];
__device__ uint8_t g_ty[G*G*RSB];
__device__ uint8_t g_tz[G*G*RSB];

__device__ __forceinline__ uint8_t quant_u8(float v) {
    int q = (int)floorf(v * 256.0f);
    return (uint8_t)min(max(q, 0), 255);
}

// One fused transform: read image[i][j][k] tile once, emit all three u8 layouts.
__global__ void trans_all_kernel(const float* __restrict__ img) {
    __shared__ float tile[32][33];
    const int i  = blockIdx.z;
    const int jb = blockIdx.x * 32;
    const int kb = blockIdx.y * 32;
    const int tx = threadIdx.x, ty = threadIdx.y;   // (32, 8)
    #pragma unroll
    for (int r = 0; r < 32; r += 8) {
        const int j = jb + ty + r;
        const float v = img[(i*G + j)*G + kb + tx];
        tile[ty + r][tx] = v;
        const uint8_t q = quant_u8(v);
        g_tx[(i*G + j)*RSB + kb + tx] = q;
        g_ty[(j*G + i)*RSB + kb + tx] = q;
    }
    __syncthreads();
    #pragma unroll
    for (int r = 0; r < 32; r += 8)
        g_tz[((kb + ty + r)*G + i)*RSB + jb + tx] = quant_u8(tile[tx][ty + r]);
}

// ---------------- TMA / mbarrier helpers (proven) ----------------
__device__ __forceinline__ void mbar_init(uint32_t mbar, uint32_t count) {
    asm volatile("mbarrier.init.shared::cta.b64 [%0], %1;" :: "r"(mbar), "r"(count) : "memory");
}
__device__ __forceinline__ void mbar_expect_tx(uint32_t mbar, uint32_t bytes) {
    asm volatile("mbarrier.arrive.expect_tx.shared::cta.b64 _, [%0], %1;"
                 :: "r"(mbar), "r"(bytes) : "memory");
}
__device__ __forceinline__ void mbar_wait(uint32_t mbar, uint32_t phase) {
    asm volatile(
        "{\n\t"
        ".reg .pred P1;\n\t"
        "LAB_WAIT_%=:\n\t"
        "mbarrier.try_wait.parity.acquire.cta.shared::cta.b64 P1, [%0], %1, 0x989680;\n\t"
        "@P1 bra LAB_DONE_%=;\n\t"
        "bra.uni LAB_WAIT_%=;\n\t"
        "LAB_DONE_%=:\n\t"
        "}"
        :: "r"(mbar), "r"(phase) : "memory");
}
__device__ __forceinline__ void bulk_g2s(uint32_t dst, const void* src, uint32_t bytes, uint32_t mbar) {
    asm volatile("cp.async.bulk.shared::cluster.global.mbarrier::complete_tx::bytes [%0], [%1], %2, [%3];"
                 :: "r"(dst), "l"(src), "r"(bytes), "r"(mbar) : "memory");
}

__global__ __launch_bounds__(THREADS, 2)
void proj_kernel(const float* __restrict__ lx,
                 const float* __restrict__ ly,
                 const float* __restrict__ lz,
                 float* __restrict__ out)
{
    extern __shared__ __align__(128) unsigned char smem_raw[];
    const uint32_t smem_base = (uint32_t)__cvta_generic_to_shared(smem_raw);
    const uint32_t mbar0 = smem_base;            // 4 mbarriers, 8 B apart
    uint8_t* sbuf = (uint8_t*)(smem_raw + 128);

    const int axis = blockIdx.y;
    const int tid  = threadIdx.x;
    const int cta_base = blockIdx.x * LPC;

    const float* lors;
    const uint8_t* vol;
    int q0, q1;
    if (axis == 0)      { lors = lx; vol = g_tx; q0 = 1; q1 = 2; }
    else if (axis == 1) { lors = ly; vol = g_ty; q0 = 0; q1 = 2; }
    else                { lors = lz; vol = g_tz; q0 = 0; q1 = 1; }

    // per-LOR params in CELL units, prefolded by -(TFRAC+1) so the window
    // anchor is floor(ua) and the fractional offset is af - ua + EOFF.
    float ua0[LPT], va0[LPT], ddx[LPT], ddy[LPT], total[LPT];
    #pragma unroll
    for (int l = 0; l < LPT; l++) {
        int gi = cta_base + l*THREADS + tid;
        int lr = gi < NL ? gi : NL - 1;
        const float* L6 = lors + lr * 6;
        float px = L6[q0], py = L6[q1];
        ddx[l] = (L6[q0+3] - px) * (1.0f/400.0f);
        ddy[l] = (L6[q1+3] - py) * (1.0f/400.0f);
        ua0[l] = fmaf(px, 0.32f, 64.0f - (TFRAC + 1.0f)) + 0.5f * ddx[l];
        va0[l] = fmaf(py, 0.32f, 64.0f - (TFRAC + 1.0f)) + 0.5f * ddy[l];
        total[l] = 0.0f;
    }

    const __half2 nCC2   = __float2half2_rn(-CC);
    const __half2 KW2C2  = __float2half2_rn(KW2C);
    const __half2 zero2  = __float2half2_rn(0.0f);
    const __half2 B10235 = __float2half2_rn(1023.5f);
    const __half2 C01    = __halves2half2(__float2half(EOFF), __float2half(EOFF + 1.0f));
    const __half2 C22    = __float2half2_rn(2.0f);

    if (tid == 0) {
        #pragma unroll
        for (int s = 0; s < NSTAGE; s++) mbar_init(mbar0 + s*8, 1);
        asm volatile("fence.proxy.async.shared::cta;" ::: "memory");
    }
    __syncthreads();
    if (tid == 0) {
        #pragma unroll
        for (int s = 0; s < NSTAGE; s++) {
            mbar_expect_tx(mbar0 + s*8, SLICE_BYTES);
            bulk_g2s(smem_base + 128 + s*SLICE_BYTES, vol + (size_t)s*GRSB, SLICE_BYTES, mbar0 + s*8);
        }
    }

    for (int kp = 0; kp < G; kp += 2) {
        const int s0 = kp & 3;
        const uint32_t ph = (kp >> 2) & 1;

        #pragma unroll
        for (int h = 0; h < 2; h++) {
            const int s = s0 + h;
            mbar_wait(mbar0 + s*8, ph);
            const uint8_t* slice = sbuf + s * GRSB;
            const float kf = (float)(kp + h);

            #pragma unroll
            for (int l = 0; l < LPT; l++) {
                const float ua = fmaf(kf, ddx[l], ua0[l]);
                const float va = fmaf(kf, ddy[l], va0[l]);

                float af = floorf(ua);
                af = fminf(fmaxf(af, 0.0f), 124.0f);
                float cf = floorf(va);
                cf = fminf(fmaxf(cf, 0.0f), 124.0f);
                const int alo = (int)af;
                const int clo = (int)cf;
                const int d   = clo & 3;
                const int cW  = clo - d;
                const uint32_t selp = 0x3210u + (uint32_t)d * 0x1111u;

                const float eR = af - ua;      // + EOFF folded into C01
                const float fR = cf - va;

                // col (f+m)^2 table, m=0..3, fully packed
                __half2 f2  = __hadd2(__float2half2_rn(fR), C01);   // (y0, y1)
                __half2 S0  = __hmul2(f2, f2);
                __half2 f2b = __hadd2(f2, C22);                     // (y2, y3)
                __half2 S1  = __hmul2(f2b, f2b);
                const __half2 P0 = h2exp2(__hmul2(S0, nCC2));
                const __half2 P1 = h2exp2(__hmul2(S1, nCC2));

                // row (e+a)^2 table, a=0..3, fully packed
                __half2 e2  = __hadd2(__float2half2_rn(eR), C01);   // (x0, x1)
                __half2 X01 = __hmul2(e2, e2);
                __half2 e2b = __hadd2(e2, C22);                     // (x2, x3)
                __half2 X23 = __hmul2(e2b, e2b);
                const __half2 W01 = h2exp2(__hmul2(X01, nCC2));
                const __half2 W23 = h2exp2(__hmul2(X23, nCC2));
                const __half2 L01 = __hsub2(KW2C2, X01);
                const __half2 L23 = __hsub2(KW2C2, X23);

                __half2 lb[4], wb[4];
                lb[0] = __low2half2(L01);  lb[1] = __high2half2(L01);
                lb[2] = __low2half2(L23);  lb[3] = __high2half2(L23);
                wb[0] = __low2half2(W01);  wb[1] = __high2half2(W01);
                wb[2] = __low2half2(W23);  wb[3] = __high2half2(W23);

                const uint8_t* rp = slice + alo * RSB + cW;
                __half2 acc2 = zero2;

                #pragma unroll
                for (int a = 0; a < 4; a++) {
                    const uint32_t w0 = *(const uint32_t*)(rp);
                    const uint32_t w1 = *(const uint32_t*)(rp + 4);
                    const uint32_t p  = __byte_perm(w0, w1, selp);
                    const uint32_t e0 = __byte_perm(p, 0x64646464u, 0x4140u);
                    const uint32_t e1 = __byte_perm(p, 0x64646464u, 0x4342u);
                    const __half2 V0 = __hsub2(*(const __half2*)&e0, B10235);
                    const __half2 V1 = __hsub2(*(const __half2*)&e1, B10235);

                    __half2 r2 = __hmul2(__hmul2(__hle2(S0, lb[a]), P0), V0);
                    r2 = __hfma2(__hmul2(__hle2(S1, lb[a]), P1), V1, r2);
                    acc2 = __hfma2(wb[a], r2, acc2);
                    rp += RSB;
                }

                const float2 fr = __half22float2(acc2);
                total[l] += fr.x + fr.y;
            }
        }

        __syncthreads();   // all warps done with stages s0, s0+1
        if (tid == 0 && kp + 4 < G) {
            mbar_expect_tx(mbar0 + s0*8, SLICE_BYTES);
            bulk_g2s(smem_base + 128 + s0*SLICE_BYTES,
                     vol + (size_t)(kp + 4)*GRSB, SLICE_BYTES, mbar0 + s0*8);
            mbar_expect_tx(mbar0 + (s0+1)*8, SLICE_BYTES);
            bulk_g2s(smem_base + 128 + (s0+1)*SLICE_BYTES,
                     vol + (size_t)(kp + 5)*GRSB, SLICE_BYTES, mbar0 + (s0+1)*8);
        }
    }

    #pragma unroll
    for (int l = 0; l < LPT; l++) {
        int gi = cta_base + l*THREADS + tid;
        if (gi < NL) {
            // path = DX * sqrt(ddx^2 + ddy^2 + 1); u8 decode scale 1/256
            float sfac = sqrtf(fmaf(ddx[l], ddx[l], fmaf(ddy[l], ddy[l], 1.0f)));
            out[axis * NL + gi] = total[l] * (DX / 256.0f) * sfac;
        }
    }
}

extern "C" void kernel_launch(void* const* d_in, const int* in_sizes, int n_in,
                              void* d_out, int out_size)
{
    (void)in_sizes; (void)n_in; (void)out_size;
    const float* image = (const float*)d_in[0];
    const float* xl    = (const float*)d_in[1];
    const float* yl    = (const float*)d_in[2];
    const float* zl    = (const float*)d_in[3];
    float* out = (float*)d_out;

    static bool attr_set = false;
    if (!attr_set) {
        cudaFuncSetAttribute(proj_kernel, cudaFuncAttributeMaxDynamicSharedMemorySize, SMEM_BYTES);
        attr_set = true;
    }

    trans_all_kernel<<<dim3(4, 4, G), dim3(32, 8)>>>(image);

    dim3 grid(NCTA, 3);
    proj_kernel<<<grid, THREADS, SMEM_BYTES>>>(xl, yl, zl, out);
}